// round 4
// baseline (speedup 1.0000x reference)
#include <cuda_runtime.h>
#include <cuda_bf16.h>
#include <cstdint>

#define N_NODES 10000
#define N_EDGES 320000
#define HID 64
#define NB 79
#define NPAD (NB * 128)          // 10112
#define NEG -3.0e38f
#define SPLIT_TILE 18432         // 128 rows * 144B padded row in smem
#define ROWB 144                 // smem row stride bytes (64 bf16 + 8 pad)

// ---------------- static device scratch ----------------
__device__ int   d_src[N_EDGES];
__device__ int   d_dst[N_EDGES];
__device__ float d_hA[N_NODES * HID];
__device__ float d_hB[N_NODES * HID];
__device__ float d_agg[N_NODES * HID];
__device__ float d_rowm[N_NODES];
__device__ float d_rowinv[N_NODES];
// 3-way bf16 split operands, linear [split][NPAD][64]
__device__ __nv_bfloat16 d_Gs[3 * NPAD * HID];
__device__ __nv_bfloat16 d_Hs[3 * NPAD * HID];
// per (col-tile, row) softmax partials
__device__ float d_pm[(size_t)NB * NPAD];
__device__ float d_ps[(size_t)NB * NPAD];
__device__ float d_L[(size_t)N_NODES * N_NODES];   // 400 MB logits scratch

// ---------------- helpers ----------------
__device__ __forceinline__ uint32_t smem_u32(const void* p) {
    uint32_t a;
    asm("{ .reg .u64 t; cvta.to.shared.u64 t, %1; cvt.u32.u64 %0, t; }" : "=r"(a) : "l"(p));
    return a;
}
__device__ __forceinline__ void ldsm4(uint32_t* r, uint32_t a) {
    asm volatile("ldmatrix.sync.aligned.m8n8.x4.shared.b16 {%0,%1,%2,%3}, [%4];"
                 : "=r"(r[0]), "=r"(r[1]), "=r"(r[2]), "=r"(r[3]) : "r"(a));
}
__device__ __forceinline__ void mma16816(float* c, const uint32_t* a, uint32_t b0, uint32_t b1) {
    asm volatile("mma.sync.aligned.m16n8k16.row.col.f32.bf16.bf16.f32 "
                 "{%0,%1,%2,%3},{%4,%5,%6,%7},{%8,%9},{%0,%1,%2,%3};"
                 : "+f"(c[0]), "+f"(c[1]), "+f"(c[2]), "+f"(c[3])
                 : "r"(a[0]), "r"(a[1]), "r"(a[2]), "r"(a[3]), "r"(b0), "r"(b1));
}

// exact 3-way bf16 split, linear layout
__device__ __forceinline__ void write_split(__nv_bfloat16* base, int n, int k, float v) {
    size_t o = (size_t)n * HID + k;
    __nv_bfloat16 b0 = __float2bfloat16(v);
    float r1 = v - __bfloat162float(b0);
    __nv_bfloat16 b1 = __float2bfloat16(r1);
    float r2 = r1 - __bfloat162float(b1);
    __nv_bfloat16 b2 = __float2bfloat16(r2);
    base[o] = b0;
    base[o + (size_t)NPAD * HID] = b1;
    base[o + (size_t)2 * NPAD * HID] = b2;
}

// =====================================================================
// Launch 1: prep = edge convert (+width detect) | zero agg | node embed | zero split tails
// =====================================================================
__global__ void prep_kernel(const unsigned* __restrict__ raw,
                            const float* __restrict__ x,
                            const float* __restrict__ Win,
                            const float* __restrict__ bin) {
    int b = blockIdx.x, tid = threadIdx.x;
    if (b < 1250) {
        __shared__ unsigned s_is64;
        if (tid < 32) {
            unsigned acc = 0;
            for (int i = tid; i < 2048; i += 32) acc |= raw[2 * i + 1];
#pragma unroll
            for (int o = 16; o; o >>= 1) acc |= __shfl_xor_sync(0xffffffffu, acc, o);
            if (tid == 0) s_is64 = (acc == 0) ? 1u : 0u;
        }
        __syncthreads();
        int e = b * 256 + tid;
        if (s_is64) {
            d_src[e] = (int)raw[2 * e];
            d_dst[e] = (int)raw[2 * (N_EDGES + e)];
        } else {
            d_src[e] = (int)raw[e];
            d_dst[e] = (int)raw[N_EDGES + e];
        }
    } else if (b < 3750) {
        int i = (b - 1250) * 256 + tid;
        d_agg[i] = 0.f;
    } else if (b < 6250) {
        int local = b - 3750;
        int sub = tid >> 6, h = tid & 63;
        int n = local * 4 + sub;
        __shared__ float xs[4][24];
        if (h < 24) xs[sub][h] = x[n * 24 + h];
        __syncthreads();
        float a = bin[h];
#pragma unroll
        for (int k = 0; k < 24; k++) a = fmaf(xs[sub][k], Win[k * HID + h], a);
        d_hA[n * HID + h] = a;
    } else {
        int s = b - 6250;                            // 0..5: zero rows [N_NODES, NPAD)
        __nv_bfloat16* zb = (s < 3) ? (d_Gs + (size_t)s * NPAD * HID)
                                    : (d_Hs + (size_t)(s - 3) * NPAD * HID);
        uint4* p = (uint4*)(zb + (size_t)N_NODES * HID);
        for (int i = tid; i < (NPAD - N_NODES) * HID / 8; i += 256)
            p[i] = make_uint4(0, 0, 0, 0);
    }
}

// =====================================================================
// Launch 2/4: agg[dst] += relu(h[src] + edge_attr@We + be)
// =====================================================================
__global__ void edge_kernel(const float* __restrict__ eattr,
                            const float* __restrict__ We,
                            const float* __restrict__ be, int sel) {
    int idx = blockIdx.x * 256 + threadIdx.x;
    int e = idx >> 4;
    int c = (idx & 15) * 4;
    const float* hin = sel ? d_hB : d_hA;
    int s = d_src[e], d = d_dst[e];
    float2 a  = *(const float2*)(eattr + 2 * e);
    float4 h4 = *(const float4*)(hin + s * HID + c);
    float4 w0 = *(const float4*)(We + c);
    float4 w1 = *(const float4*)(We + HID + c);
    float4 b4 = *(const float4*)(be + c);
    float v0 = fmaxf(h4.x + fmaf(a.x, w0.x, fmaf(a.y, w1.x, b4.x)), 0.f);
    float v1 = fmaxf(h4.y + fmaf(a.x, w0.y, fmaf(a.y, w1.y, b4.y)), 0.f);
    float v2 = fmaxf(h4.z + fmaf(a.x, w0.z, fmaf(a.y, w1.z, b4.z)), 0.f);
    float v3 = fmaxf(h4.w + fmaf(a.x, w0.w, fmaf(a.y, w1.w, b4.w)), 0.f);
    asm volatile("red.global.add.v4.f32 [%0], {%1,%2,%3,%4};"
                 :: "l"(d_agg + d * HID + c), "f"(v0), "f"(v1), "f"(v2), "f"(v3) : "memory");
}

// =====================================================================
// Launch 3: layer-1 MLP (relu out) + re-zero agg
// =====================================================================
__global__ void mlp1_kernel(const float* __restrict__ W1, const float* __restrict__ b1,
                            const float* __restrict__ W2, const float* __restrict__ b2) {
    int n = blockIdx.x, h = threadIdx.x;
    __shared__ float zs[HID], ts[HID];
    zs[h] = d_hA[n * HID + h] + d_agg[n * HID + h];
    d_agg[n * HID + h] = 0.f;
    __syncthreads();
    float t = b1[h];
#pragma unroll 16
    for (int k = 0; k < HID; k++) t = fmaf(zs[k], W1[k * HID + h], t);
    ts[h] = fmaxf(t, 0.f);
    __syncthreads();
    float o = b2[h];
#pragma unroll 16
    for (int k = 0; k < HID; k++) o = fmaf(ts[k], W2[k * HID + h], o);
    d_hB[n * HID + h] = fmaxf(o, 0.f);
}

// =====================================================================
// Launch 5: layer-2 MLP + g = h@M + write split operands
// =====================================================================
__global__ void mlp2_kernel(const float* __restrict__ W1, const float* __restrict__ b1,
                            const float* __restrict__ W2, const float* __restrict__ b2,
                            const float* __restrict__ M) {
    int n = blockIdx.x, h = threadIdx.x;
    __shared__ float zs[HID], ts[HID];
    zs[h] = d_hB[n * HID + h] + d_agg[n * HID + h];
    __syncthreads();
    float t = b1[h];
#pragma unroll 16
    for (int k = 0; k < HID; k++) t = fmaf(zs[k], W1[k * HID + h], t);
    ts[h] = fmaxf(t, 0.f);
    __syncthreads();
    float o = b2[h];
#pragma unroll 16
    for (int k = 0; k < HID; k++) o = fmaf(ts[k], W2[k * HID + h], o);
    __syncthreads();
    zs[h] = o;
    __syncthreads();
    float g = 0.f;
#pragma unroll 16
    for (int k = 0; k < HID; k++) g = fmaf(zs[k], M[k * HID + h], g);
    write_split(d_Hs, n, h, o);
    write_split(d_Gs, n, h, g);
}

// =====================================================================
// Launch 6: L = G @ H^T via mma.sync bf16 3-split + fused softmax partials
// CTA: 128x128 tile, 8 warps (2m x 4n), each warp 64x32
// =====================================================================
__global__ void __launch_bounds__(256, 2) gemm_kernel() {
    extern __shared__ char smem[];
    uint32_t sbase = smem_u32(smem);
    int tid = threadIdx.x;
    int wid = tid >> 5, lane = tid & 31;
    int i0 = blockIdx.y * 128, j0 = blockIdx.x * 128;

    // load 6 split tiles (A: G splits 0-2, B: H splits 0-2), insert 16B/row pad
    {
        const uint4* gs = (const uint4*)d_Gs;
        const uint4* hs = (const uint4*)d_Hs;
        for (int t = tid; t < 6144; t += 256) {
            int s = t >> 10, o = t & 1023;
            int row = o >> 3, q = o & 7;
            uint4 v = (s < 3) ? gs[(size_t)s * NPAD * 8 + (size_t)(i0 + row) * 8 + q]
                              : hs[(size_t)(s - 3) * NPAD * 8 + (size_t)(j0 + row) * 8 + q];
            *(uint4*)(smem + s * SPLIT_TILE + row * ROWB + q * 16) = v;
        }
    }
    __syncthreads();

    int wm = wid >> 2, wn = wid & 3;
    float acc[4][4][4];
#pragma unroll
    for (int a = 0; a < 4; a++)
#pragma unroll
        for (int b = 0; b < 4; b++)
#pragma unroll
            for (int c = 0; c < 4; c++) acc[a][b][c] = 0.f;

    const int pa[6] = {0, 0, 1, 1, 0, 2};
    const int pb[6] = {0, 1, 0, 1, 2, 0};
    // A addressing: lanes 0-15 -> m rows 0-15 @ k-bytes 0; lanes 16-31 -> same rows @ k-bytes 16
    uint32_t lrow = (lane & 15), lcol = (lane >> 4) * 16;
    // B addressing (non-trans): 4 tiles = (n-octet, k-octet)
    int bg = lane >> 3, br = lane & 7;
    int b_noff = (bg >> 1) * 8 + br;        // n-offset within 16-block
    int b_koff = (bg & 1) * 16;             // k-byte offset within 32-byte k16

#pragma unroll
    for (int s = 0; s < 6; s++) {
        uint32_t abase = sbase + pa[s] * SPLIT_TILE + (wm * 64 + lrow) * ROWB + lcol;
        uint32_t bbase = sbase + (3 + pb[s]) * SPLIT_TILE + (wn * 32 + b_noff) * ROWB + b_koff;
#pragma unroll
        for (int ks = 0; ks < 4; ks++) {
            uint32_t a[4][4];
#pragma unroll
            for (int mi = 0; mi < 4; mi++) ldsm4(a[mi], abase + mi * 16 * ROWB + ks * 32);
            // B fragments: H stored [n][k] == col-major k16n8 -> non-trans ldmatrix.
            // bfr[bi] regs: {octet0 b0, octet0 b1, octet1 b0, octet1 b1}, octets at n = bi*16 + {0,8}
            uint32_t bfr[2][4];
#pragma unroll
            for (int bi = 0; bi < 2; bi++)
                ldsm4(bfr[bi], bbase + bi * 16 * ROWB + ks * 32);
#pragma unroll
            for (int mi = 0; mi < 4; mi++)
#pragma unroll
                for (int ni = 0; ni < 4; ni++) {
                    int bi = ni >> 1, h = ni & 1;
                    mma16816(acc[mi][ni], a[mi], bfr[bi][h * 2], bfr[bi][h * 2 + 1]);
                }
        }
    }
    __syncthreads();          // operand smem dead; reuse for partial reduction

    float2* part = (float2*)smem;   // [128][4]
    int q = lane >> 2, t2 = (lane & 3) * 2;
    bool edge_j = (blockIdx.x == NB - 1);

    // store L + per-row (m, s) partials over this warp's 32 cols
#pragma unroll
    for (int mi = 0; mi < 4; mi++) {
#pragma unroll
        for (int half = 0; half < 2; half++) {
            int rl = wm * 64 + mi * 16 + q + half * 8;
            int gr = i0 + rl;
            float m = NEG, ssum = 0.f;
#pragma unroll
            for (int ni = 0; ni < 4; ni++) {
                int cg = j0 + wn * 32 + ni * 8 + t2;
                float v0 = acc[mi][ni][half * 2], v1 = acc[mi][ni][half * 2 + 1];
                bool ok = !edge_j || (cg < N_NODES);
                if (ok) {
                    m = fmaxf(m, fmaxf(v0, v1));
                    if (gr < N_NODES)
                        *(float2*)(d_L + (size_t)gr * N_NODES + cg) = make_float2(v0, v1);
                }
            }
            if (m > NEG) {
#pragma unroll
                for (int ni = 0; ni < 4; ni++) {
                    int cg = j0 + wn * 32 + ni * 8 + t2;
                    bool ok = !edge_j || (cg < N_NODES);
                    if (ok)
                        ssum += __expf(acc[mi][ni][half * 2] - m) +
                                __expf(acc[mi][ni][half * 2 + 1] - m);
                }
            }
#pragma unroll
            for (int off = 1; off < 4; off <<= 1) {
                float m2 = __shfl_xor_sync(0xffffffffu, m, off);
                float s2 = __shfl_xor_sync(0xffffffffu, ssum, off);
                float mm = fmaxf(m, m2);
                ssum = ssum * __expf(m - mm) + s2 * __expf(m2 - mm);
                m = mm;
            }
            if ((lane & 3) == 0) part[rl * 4 + wn] = make_float2(m, ssum);
        }
    }
    __syncthreads();

    if (tid < 128) {
        float m = NEG, ssum = 0.f;
#pragma unroll
        for (int w = 0; w < 4; w++) {
            float2 p = part[tid * 4 + w];
            float mm = fmaxf(m, p.x);
            ssum = ssum * __expf(m - mm) + p.y * __expf(p.x - mm);
            m = mm;
        }
        d_pm[(size_t)blockIdx.x * NPAD + i0 + tid] = m;
        d_ps[(size_t)blockIdx.x * NPAD + i0 + tid] = ssum;
    }
}

// =====================================================================
// Launch 7: combine 79 tile-partials per row -> rowm, rowinv
// =====================================================================
__global__ void combine_kernel() {
    int r = blockIdx.x * 256 + threadIdx.x;
    if (r >= N_NODES) return;
    float m = NEG, s = 0.f;
    for (int t = 0; t < NB; t++) {
        float m2 = d_pm[(size_t)t * NPAD + r];
        float s2 = d_ps[(size_t)t * NPAD + r];
        float mm = fmaxf(m, m2);
        s = s * __expf(m - mm) + s2 * __expf(m2 - mm);
        m = mm;
    }
    d_rowm[r] = m;
    d_rowinv[r] = 1.f / s;
}

// =====================================================================
// Launch 8: out = exp(L - m) * inv
// =====================================================================
__global__ void finalize_kernel(float* __restrict__ out) {
    int i  = blockIdx.y;
    int j4 = blockIdx.x * 256 + threadIdx.x;
    if (j4 >= N_NODES / 4) return;
    float m = d_rowm[i], inv = d_rowinv[i];
    size_t idx = (size_t)i * (N_NODES / 4) + j4;
    float4 v = ((const float4*)d_L)[idx];
    float4 o;
    o.x = __expf(v.x - m) * inv;
    o.y = __expf(v.y - m) * inv;
    o.z = __expf(v.z - m) * inv;
    o.w = __expf(v.w - m) * inv;
    ((float4*)out)[idx] = o;
}

extern "C" void kernel_launch(void* const* d_in, const int* in_sizes, int n_in,
                              void* d_out, int out_size) {
    const float*    x     = (const float*)d_in[0];
    const float*    eattr = (const float*)d_in[1];
    const unsigned* eidx  = (const unsigned*)d_in[2];
    const float*    Win   = (const float*)d_in[3];
    const float*    bin   = (const float*)d_in[4];
    const float*    We    = (const float*)d_in[5];
    const float*    be    = (const float*)d_in[6];
    const float*    W1    = (const float*)d_in[7];
    const float*    b1    = (const float*)d_in[8];
    const float*    W2    = (const float*)d_in[9];
    const float*    b2    = (const float*)d_in[10];
    const float*    M     = (const float*)d_in[11];
    float*          out   = (float*)d_out;

    const int GEMM_SMEM = 6 * SPLIT_TILE;           // 110592
    cudaFuncSetAttribute(gemm_kernel, cudaFuncAttributeMaxDynamicSharedMemorySize, GEMM_SMEM);

    prep_kernel<<<6256, 256>>>(eidx, x, Win, bin);                     // #1
    edge_kernel<<<N_EDGES * 16 / 256, 256>>>(eattr, We, be, 0);        // #2
    mlp1_kernel<<<N_NODES, HID>>>(W1, b1, W2, b2);                     // #3
    edge_kernel<<<N_EDGES * 16 / 256, 256>>>(eattr, We, be, 1);        // #4
    mlp2_kernel<<<N_NODES, HID>>>(W1, b1, W2, b2, M);                  // #5
    dim3 ggrid(NB, NB);
    gemm_kernel<<<ggrid, 256, GEMM_SMEM>>>();                          // #6
    combine_kernel<<<(N_NODES + 255) / 256, 256>>>();                  // #7
    dim3 fgrid((N_NODES / 4 + 255) / 256, N_NODES);
    finalize_kernel<<<fgrid, 256>>>(out);                              // #8
}

// round 5
// speedup vs baseline: 1.2948x; 1.2948x over previous
#include <cuda_runtime.h>
#include <cuda_bf16.h>
#include <cstdint>

#define N_NODES 10000
#define N_EDGES 320000
#define HID 64
#define NB 79
#define NPAD (NB * 128)          // 10112
#define NEG -3.0e38f
#define SPLIT_TILE 18432         // 128 rows * 144B padded row in smem
#define ROWB 144                 // smem row stride bytes (64 bf16 + 8 pad)

// ---------------- static device scratch ----------------
__device__ int   d_src[N_EDGES];
__device__ int   d_dst[N_EDGES];
__device__ float d_hA[N_NODES * HID];
__device__ float d_hB[N_NODES * HID];
__device__ float d_agg[N_NODES * HID];
__device__ float d_rowm[N_NODES];
__device__ float d_rowinv[N_NODES];
// 2-way bf16 split operands, linear [split][NPAD][64]
__device__ __nv_bfloat16 d_Gs[2 * NPAD * HID];
__device__ __nv_bfloat16 d_Hs[2 * NPAD * HID];
// per (col-tile, row) softmax partials
__device__ float d_pm[(size_t)NB * NPAD];
__device__ float d_ps[(size_t)NB * NPAD];
__device__ float d_L[(size_t)N_NODES * N_NODES];   // 400 MB logits scratch

// ---------------- helpers ----------------
__device__ __forceinline__ uint32_t smem_u32(const void* p) {
    uint32_t a;
    asm("{ .reg .u64 t; cvta.to.shared.u64 t, %1; cvt.u32.u64 %0, t; }" : "=r"(a) : "l"(p));
    return a;
}
__device__ __forceinline__ void ldsm4(uint32_t* r, uint32_t a) {
    asm volatile("ldmatrix.sync.aligned.m8n8.x4.shared.b16 {%0,%1,%2,%3}, [%4];"
                 : "=r"(r[0]), "=r"(r[1]), "=r"(r[2]), "=r"(r[3]) : "r"(a));
}
__device__ __forceinline__ void mma16816(float* c, const uint32_t* a, uint32_t b0, uint32_t b1) {
    asm volatile("mma.sync.aligned.m16n8k16.row.col.f32.bf16.bf16.f32 "
                 "{%0,%1,%2,%3},{%4,%5,%6,%7},{%8,%9},{%0,%1,%2,%3};"
                 : "+f"(c[0]), "+f"(c[1]), "+f"(c[2]), "+f"(c[3])
                 : "r"(a[0]), "r"(a[1]), "r"(a[2]), "r"(a[3]), "r"(b0), "r"(b1));
}

// exact 2-way bf16 split (hi + lo), linear layout
__device__ __forceinline__ void write_split(__nv_bfloat16* base, int n, int k, float v) {
    size_t o = (size_t)n * HID + k;
    __nv_bfloat16 b0 = __float2bfloat16(v);
    float r1 = v - __bfloat162float(b0);
    __nv_bfloat16 b1 = __float2bfloat16(r1);
    base[o] = b0;
    base[o + (size_t)NPAD * HID] = b1;
}

// =====================================================================
// Launch 1: prep = edge convert (+width detect) | zero agg | node embed | zero split tails
// =====================================================================
__global__ void prep_kernel(const unsigned* __restrict__ raw,
                            const float* __restrict__ x,
                            const float* __restrict__ Win,
                            const float* __restrict__ bin) {
    int b = blockIdx.x, tid = threadIdx.x;
    if (b < 1250) {
        __shared__ unsigned s_is64;
        if (tid < 32) {
            unsigned acc = 0;
            for (int i = tid; i < 2048; i += 32) acc |= raw[2 * i + 1];
#pragma unroll
            for (int o = 16; o; o >>= 1) acc |= __shfl_xor_sync(0xffffffffu, acc, o);
            if (tid == 0) s_is64 = (acc == 0) ? 1u : 0u;
        }
        __syncthreads();
        int e = b * 256 + tid;
        if (s_is64) {
            d_src[e] = (int)raw[2 * e];
            d_dst[e] = (int)raw[2 * (N_EDGES + e)];
        } else {
            d_src[e] = (int)raw[e];
            d_dst[e] = (int)raw[N_EDGES + e];
        }
    } else if (b < 3750) {
        int i = (b - 1250) * 256 + tid;
        d_agg[i] = 0.f;
    } else if (b < 6250) {
        int local = b - 3750;
        int sub = tid >> 6, h = tid & 63;
        int n = local * 4 + sub;
        __shared__ float xs[4][24];
        if (h < 24) xs[sub][h] = x[n * 24 + h];
        __syncthreads();
        float a = bin[h];
#pragma unroll
        for (int k = 0; k < 24; k++) a = fmaf(xs[sub][k], Win[k * HID + h], a);
        d_hA[n * HID + h] = a;
    } else {
        int s = b - 6250;                            // 0..3: zero rows [N_NODES, NPAD)
        __nv_bfloat16* zb = (s < 2) ? (d_Gs + (size_t)s * NPAD * HID)
                                    : (d_Hs + (size_t)(s - 2) * NPAD * HID);
        uint4* p = (uint4*)(zb + (size_t)N_NODES * HID);
        for (int i = tid; i < (NPAD - N_NODES) * HID / 8; i += 256)
            p[i] = make_uint4(0, 0, 0, 0);
    }
}

// =====================================================================
// Launch 2/4: agg[dst] += relu(h[src] + edge_attr@We + be)
// =====================================================================
__global__ void edge_kernel(const float* __restrict__ eattr,
                            const float* __restrict__ We,
                            const float* __restrict__ be, int sel) {
    int idx = blockIdx.x * 256 + threadIdx.x;
    int e = idx >> 4;
    int c = (idx & 15) * 4;
    const float* hin = sel ? d_hB : d_hA;
    int s = d_src[e], d = d_dst[e];
    float2 a  = *(const float2*)(eattr + 2 * e);
    float4 h4 = *(const float4*)(hin + s * HID + c);
    float4 w0 = *(const float4*)(We + c);
    float4 w1 = *(const float4*)(We + HID + c);
    float4 b4 = *(const float4*)(be + c);
    float v0 = fmaxf(h4.x + fmaf(a.x, w0.x, fmaf(a.y, w1.x, b4.x)), 0.f);
    float v1 = fmaxf(h4.y + fmaf(a.x, w0.y, fmaf(a.y, w1.y, b4.y)), 0.f);
    float v2 = fmaxf(h4.z + fmaf(a.x, w0.z, fmaf(a.y, w1.z, b4.z)), 0.f);
    float v3 = fmaxf(h4.w + fmaf(a.x, w0.w, fmaf(a.y, w1.w, b4.w)), 0.f);
    asm volatile("red.global.add.v4.f32 [%0], {%1,%2,%3,%4};"
                 :: "l"(d_agg + d * HID + c), "f"(v0), "f"(v1), "f"(v2), "f"(v3) : "memory");
}

// =====================================================================
// Launch 3: layer-1 MLP (relu out) + re-zero agg
// =====================================================================
__global__ void mlp1_kernel(const float* __restrict__ W1, const float* __restrict__ b1,
                            const float* __restrict__ W2, const float* __restrict__ b2) {
    int n = blockIdx.x, h = threadIdx.x;
    __shared__ float zs[HID], ts[HID];
    zs[h] = d_hA[n * HID + h] + d_agg[n * HID + h];
    d_agg[n * HID + h] = 0.f;
    __syncthreads();
    float t = b1[h];
#pragma unroll 16
    for (int k = 0; k < HID; k++) t = fmaf(zs[k], W1[k * HID + h], t);
    ts[h] = fmaxf(t, 0.f);
    __syncthreads();
    float o = b2[h];
#pragma unroll 16
    for (int k = 0; k < HID; k++) o = fmaf(ts[k], W2[k * HID + h], o);
    d_hB[n * HID + h] = fmaxf(o, 0.f);
}

// =====================================================================
// Launch 5: layer-2 MLP + g = h@M + write split operands
// =====================================================================
__global__ void mlp2_kernel(const float* __restrict__ W1, const float* __restrict__ b1,
                            const float* __restrict__ W2, const float* __restrict__ b2,
                            const float* __restrict__ M) {
    int n = blockIdx.x, h = threadIdx.x;
    __shared__ float zs[HID], ts[HID];
    zs[h] = d_hB[n * HID + h] + d_agg[n * HID + h];
    __syncthreads();
    float t = b1[h];
#pragma unroll 16
    for (int k = 0; k < HID; k++) t = fmaf(zs[k], W1[k * HID + h], t);
    ts[h] = fmaxf(t, 0.f);
    __syncthreads();
    float o = b2[h];
#pragma unroll 16
    for (int k = 0; k < HID; k++) o = fmaf(ts[k], W2[k * HID + h], o);
    __syncthreads();
    zs[h] = o;
    __syncthreads();
    float g = 0.f;
#pragma unroll 16
    for (int k = 0; k < HID; k++) g = fmaf(zs[k], M[k * HID + h], g);
    write_split(d_Hs, n, h, o);
    write_split(d_Gs, n, h, g);
}

// =====================================================================
// Launch 6: L = G @ H^T via mma.sync, 3-term 2-way-split bf16 + fused softmax partials
// CTA: 128x128 tile, 8 warps (2m x 4n), each warp 64x32
// =====================================================================
__global__ void __launch_bounds__(256, 2) gemm_kernel() {
    extern __shared__ char smem[];
    uint32_t sbase = smem_u32(smem);
    int tid = threadIdx.x;
    int wid = tid >> 5, lane = tid & 31;
    int i0 = blockIdx.y * 128, j0 = blockIdx.x * 128;

    // load 4 split tiles (A: G0,G1 ; B: H0,H1), insert 16B/row pad
    {
        const uint4* gs = (const uint4*)d_Gs;
        const uint4* hs = (const uint4*)d_Hs;
        for (int t = tid; t < 4096; t += 256) {
            int s = t >> 10, o = t & 1023;
            int row = o >> 3, q = o & 7;
            uint4 v = (s < 2) ? gs[(size_t)s * NPAD * 8 + (size_t)(i0 + row) * 8 + q]
                              : hs[(size_t)(s - 2) * NPAD * 8 + (size_t)(j0 + row) * 8 + q];
            *(uint4*)(smem + s * SPLIT_TILE + row * ROWB + q * 16) = v;
        }
    }
    __syncthreads();

    int wm = wid >> 2, wn = wid & 3;
    float acc[4][4][4];
#pragma unroll
    for (int a = 0; a < 4; a++)
#pragma unroll
        for (int b = 0; b < 4; b++)
#pragma unroll
            for (int c = 0; c < 4; c++) acc[a][b][c] = 0.f;

    const int pa[3] = {0, 0, 1};
    const int pb[3] = {0, 1, 0};
    // A addressing: lanes 0-15 -> m rows 0-15 @ k-bytes 0; lanes 16-31 -> same rows @ k-bytes 16
    uint32_t lrow = (lane & 15), lcol = (lane >> 4) * 16;
    // B addressing (non-trans): 4 tiles = (n-octet, k-octet)
    int bg = lane >> 3, br = lane & 7;
    int b_noff = (bg >> 1) * 8 + br;        // n-offset within 16-block
    int b_koff = (bg & 1) * 16;             // k-byte offset within 32-byte k16

#pragma unroll
    for (int s = 0; s < 3; s++) {
        uint32_t abase = sbase + pa[s] * SPLIT_TILE + (wm * 64 + lrow) * ROWB + lcol;
        uint32_t bbase = sbase + (2 + pb[s]) * SPLIT_TILE + (wn * 32 + b_noff) * ROWB + b_koff;
#pragma unroll
        for (int ks = 0; ks < 4; ks++) {
            uint32_t a[4][4];
#pragma unroll
            for (int mi = 0; mi < 4; mi++) ldsm4(a[mi], abase + mi * 16 * ROWB + ks * 32);
            // B fragments: H stored [n][k] == col-major k16n8 -> non-trans ldmatrix.
            uint32_t bfr[2][4];
#pragma unroll
            for (int bi = 0; bi < 2; bi++)
                ldsm4(bfr[bi], bbase + bi * 16 * ROWB + ks * 32);
#pragma unroll
            for (int mi = 0; mi < 4; mi++)
#pragma unroll
                for (int ni = 0; ni < 4; ni++) {
                    int bi = ni >> 1, h = ni & 1;
                    mma16816(acc[mi][ni], a[mi], bfr[bi][h * 2], bfr[bi][h * 2 + 1]);
                }
        }
    }
    __syncthreads();          // operand smem dead; reuse for partial reduction

    float2* part = (float2*)smem;   // [128][4]
    int q = lane >> 2, t2 = (lane & 3) * 2;
    bool edge_j = (blockIdx.x == NB - 1);

    // store L + per-row (m, s) partials over this warp's 32 cols
#pragma unroll
    for (int mi = 0; mi < 4; mi++) {
#pragma unroll
        for (int half = 0; half < 2; half++) {
            int rl = wm * 64 + mi * 16 + q + half * 8;
            int gr = i0 + rl;
            float m = NEG, ssum = 0.f;
#pragma unroll
            for (int ni = 0; ni < 4; ni++) {
                int cg = j0 + wn * 32 + ni * 8 + t2;
                float v0 = acc[mi][ni][half * 2], v1 = acc[mi][ni][half * 2 + 1];
                bool ok = !edge_j || (cg < N_NODES);
                if (ok) {
                    m = fmaxf(m, fmaxf(v0, v1));
                    if (gr < N_NODES)
                        *(float2*)(d_L + (size_t)gr * N_NODES + cg) = make_float2(v0, v1);
                }
            }
            if (m > NEG) {
#pragma unroll
                for (int ni = 0; ni < 4; ni++) {
                    int cg = j0 + wn * 32 + ni * 8 + t2;
                    bool ok = !edge_j || (cg < N_NODES);
                    if (ok)
                        ssum += __expf(acc[mi][ni][half * 2] - m) +
                                __expf(acc[mi][ni][half * 2 + 1] - m);
                }
            }
#pragma unroll
            for (int off = 1; off < 4; off <<= 1) {
                float m2 = __shfl_xor_sync(0xffffffffu, m, off);
                float s2 = __shfl_xor_sync(0xffffffffu, ssum, off);
                float mm = fmaxf(m, m2);
                ssum = ssum * __expf(m - mm) + s2 * __expf(m2 - mm);
                m = mm;
            }
            if ((lane & 3) == 0) part[rl * 4 + wn] = make_float2(m, ssum);
        }
    }
    __syncthreads();

    if (tid < 128) {
        float m = NEG, ssum = 0.f;
#pragma unroll
        for (int w = 0; w < 4; w++) {
            float2 p = part[tid * 4 + w];
            float mm = fmaxf(m, p.x);
            ssum = ssum * __expf(m - mm) + p.y * __expf(p.x - mm);
            m = mm;
        }
        d_pm[(size_t)blockIdx.x * NPAD + i0 + tid] = m;
        d_ps[(size_t)blockIdx.x * NPAD + i0 + tid] = ssum;
    }
}

// =====================================================================
// Launch 7: combine 79 tile-partials per row -> rowm, rowinv
// =====================================================================
__global__ void combine_kernel() {
    int r = blockIdx.x * 256 + threadIdx.x;
    if (r >= N_NODES) return;
    float m = NEG, s = 0.f;
    for (int t = 0; t < NB; t++) {
        float m2 = d_pm[(size_t)t * NPAD + r];
        float s2 = d_ps[(size_t)t * NPAD + r];
        float mm = fmaxf(m, m2);
        s = s * __expf(m - mm) + s2 * __expf(m2 - mm);
        m = mm;
    }
    d_rowm[r] = m;
    d_rowinv[r] = 1.f / s;
}

// =====================================================================
// Launch 8: out = exp(L - m) * inv
// =====================================================================
__global__ void finalize_kernel(float* __restrict__ out) {
    int i  = blockIdx.y;
    int j4 = blockIdx.x * 256 + threadIdx.x;
    if (j4 >= N_NODES / 4) return;
    float m = d_rowm[i], inv = d_rowinv[i];
    size_t idx = (size_t)i * (N_NODES / 4) + j4;
    float4 v = ((const float4*)d_L)[idx];
    float4 o;
    o.x = __expf(v.x - m) * inv;
    o.y = __expf(v.y - m) * inv;
    o.z = __expf(v.z - m) * inv;
    o.w = __expf(v.w - m) * inv;
    ((float4*)out)[idx] = o;
}

extern "C" void kernel_launch(void* const* d_in, const int* in_sizes, int n_in,
                              void* d_out, int out_size) {
    const float*    x     = (const float*)d_in[0];
    const float*    eattr = (const float*)d_in[1];
    const unsigned* eidx  = (const unsigned*)d_in[2];
    const float*    Win   = (const float*)d_in[3];
    const float*    bin   = (const float*)d_in[4];
    const float*    We    = (const float*)d_in[5];
    const float*    be    = (const float*)d_in[6];
    const float*    W1    = (const float*)d_in[7];
    const float*    b1    = (const float*)d_in[8];
    const float*    W2    = (const float*)d_in[9];
    const float*    b2    = (const float*)d_in[10];
    const float*    M     = (const float*)d_in[11];
    float*          out   = (float*)d_out;

    const int GEMM_SMEM = 4 * SPLIT_TILE;           // 73728
    cudaFuncSetAttribute(gemm_kernel, cudaFuncAttributeMaxDynamicSharedMemorySize, GEMM_SMEM);

    prep_kernel<<<6254, 256>>>(eidx, x, Win, bin);                     // #1
    edge_kernel<<<N_EDGES * 16 / 256, 256>>>(eattr, We, be, 0);        // #2
    mlp1_kernel<<<N_NODES, HID>>>(W1, b1, W2, b2);                     // #3
    edge_kernel<<<N_EDGES * 16 / 256, 256>>>(eattr, We, be, 1);        // #4
    mlp2_kernel<<<N_NODES, HID>>>(W1, b1, W2, b2, M);                  // #5
    dim3 ggrid(NB, NB);
    gemm_kernel<<<ggrid, 256, GEMM_SMEM>>>();                          // #6
    combine_kernel<<<(N_NODES + 255) / 256, 256>>>();                  // #7
    dim3 fgrid((N_NODES / 4 + 255) / 256, N_NODES);
    finalize_kernel<<<fgrid, 256>>>(out);                              // #8
}

// round 7
// speedup vs baseline: 1.3919x; 1.0750x over previous
#include <cuda_runtime.h>
#include <cuda_fp16.h>
#include <cstdint>

#define N_NODES 10000
#define N_EDGES 320000
#define HID 64
#define NB 79
#define NPAD (NB * 128)          // 10112
#define NEG -3.0e38f
#define SPLIT_TILE 18432         // 128 rows * 144B padded row in smem
#define ROWB 144                 // smem row stride bytes (64 fp16 + 16 pad)
#define NCT (NB * 4)             // 316 col-blocks of 32

// ---------------- static device scratch ----------------
__device__ int   d_src[N_EDGES];
__device__ int   d_dst[N_EDGES];
__device__ float d_hA[N_NODES * HID];
__device__ float d_hB[N_NODES * HID];
__device__ float d_agg[N_NODES * HID];
// operands: G single fp16 plane; H 2-way fp16 split
__device__ __half d_Gs[NPAD * HID];
__device__ __half d_Hs[2 * NPAD * HID];
// per (32-col-block, row) softmax partials + factors
__device__ float d_pm[(size_t)NCT * NPAD];
__device__ float d_ps[(size_t)NCT * NPAD];
__device__ float d_pf[(size_t)NCT * NPAD];
__device__ __half d_E[(size_t)N_NODES * N_NODES];  // 200 MB exp scratch

// ---------------- helpers ----------------
__device__ __forceinline__ uint32_t smem_u32(const void* p) {
    uint32_t a;
    asm("{ .reg .u64 t; cvta.to.shared.u64 t, %1; cvt.u32.u64 %0, t; }" : "=r"(a) : "l"(p));
    return a;
}
__device__ __forceinline__ void ldsm4(uint32_t* r, uint32_t a) {
    asm volatile("ldmatrix.sync.aligned.m8n8.x4.shared.b16 {%0,%1,%2,%3}, [%4];"
                 : "=r"(r[0]), "=r"(r[1]), "=r"(r[2]), "=r"(r[3]) : "r"(a));
}
__device__ __forceinline__ void mma16816(float* c, const uint32_t* a, uint32_t b0, uint32_t b1) {
    asm volatile("mma.sync.aligned.m16n8k16.row.col.f32.f16.f16.f32 "
                 "{%0,%1,%2,%3},{%4,%5,%6,%7},{%8,%9},{%0,%1,%2,%3};"
                 : "+f"(c[0]), "+f"(c[1]), "+f"(c[2]), "+f"(c[3])
                 : "r"(a[0]), "r"(a[1]), "r"(a[2]), "r"(a[3]), "r"(b0), "r"(b1));
}

// =====================================================================
// Launch 1: prep = edge convert (+width detect) | zero agg | node embed | zero split tails
// =====================================================================
__global__ void prep_kernel(const unsigned* __restrict__ raw,
                            const float* __restrict__ x,
                            const float* __restrict__ Win,
                            const float* __restrict__ bin) {
    int b = blockIdx.x, tid = threadIdx.x;
    if (b < 1250) {
        __shared__ unsigned s_is64;
        if (tid < 32) {
            unsigned acc = 0;
            for (int i = tid; i < 2048; i += 32) acc |= raw[2 * i + 1];
#pragma unroll
            for (int o = 16; o; o >>= 1) acc |= __shfl_xor_sync(0xffffffffu, acc, o);
            if (tid == 0) s_is64 = (acc == 0) ? 1u : 0u;
        }
        __syncthreads();
        int e = b * 256 + tid;
        if (s_is64) {
            d_src[e] = (int)raw[2 * e];
            d_dst[e] = (int)raw[2 * (N_EDGES + e)];
        } else {
            d_src[e] = (int)raw[e];
            d_dst[e] = (int)raw[N_EDGES + e];
        }
    } else if (b < 3750) {
        int i = (b - 1250) * 256 + tid;
        d_agg[i] = 0.f;
    } else if (b < 6250) {
        int local = b - 3750;
        int sub = tid >> 6, h = tid & 63;
        int n = local * 4 + sub;
        __shared__ float xs[4][24];
        if (h < 24) xs[sub][h] = x[n * 24 + h];
        __syncthreads();
        float a = bin[h];
#pragma unroll
        for (int k = 0; k < 24; k++) a = fmaf(xs[sub][k], Win[k * HID + h], a);
        d_hA[n * HID + h] = a;
    } else {
        int s = b - 6250;                            // 0..2: zero rows [N_NODES, NPAD)
        __half* zb = (s == 0) ? d_Gs : (d_Hs + (size_t)(s - 1) * NPAD * HID);
        uint4* p = (uint4*)(zb + (size_t)N_NODES * HID);
        for (int i = tid; i < (NPAD - N_NODES) * HID / 8; i += 256)
            p[i] = make_uint4(0, 0, 0, 0);
    }
}

// =====================================================================
// Launch 2/4: agg[dst] += relu(h[src] + edge_attr@We + be)
// =====================================================================
__global__ void edge_kernel(const float* __restrict__ eattr,
                            const float* __restrict__ We,
                            const float* __restrict__ be, int sel) {
    int idx = blockIdx.x * 256 + threadIdx.x;
    int e = idx >> 4;
    int c = (idx & 15) * 4;
    const float* hin = sel ? d_hB : d_hA;
    int s = d_src[e], d = d_dst[e];
    float2 a  = *(const float2*)(eattr + 2 * e);
    float4 h4 = *(const float4*)(hin + s * HID + c);
    float4 w0 = *(const float4*)(We + c);
    float4 w1 = *(const float4*)(We + HID + c);
    float4 b4 = *(const float4*)(be + c);
    float v0 = fmaxf(h4.x + fmaf(a.x, w0.x, fmaf(a.y, w1.x, b4.x)), 0.f);
    float v1 = fmaxf(h4.y + fmaf(a.x, w0.y, fmaf(a.y, w1.y, b4.y)), 0.f);
    float v2 = fmaxf(h4.z + fmaf(a.x, w0.z, fmaf(a.y, w1.z, b4.z)), 0.f);
    float v3 = fmaxf(h4.w + fmaf(a.x, w0.w, fmaf(a.y, w1.w, b4.w)), 0.f);
    asm volatile("red.global.add.v4.f32 [%0], {%1,%2,%3,%4};"
                 :: "l"(d_agg + d * HID + c), "f"(v0), "f"(v1), "f"(v2), "f"(v3) : "memory");
}

// =====================================================================
// Launch 3: layer-1 MLP (relu out) + re-zero agg
// =====================================================================
__global__ void mlp1_kernel(const float* __restrict__ W1, const float* __restrict__ b1,
                            const float* __restrict__ W2, const float* __restrict__ b2) {
    int n = blockIdx.x, h = threadIdx.x;
    __shared__ float zs[HID], ts[HID];
    zs[h] = d_hA[n * HID + h] + d_agg[n * HID + h];
    d_agg[n * HID + h] = 0.f;
    __syncthreads();
    float t = b1[h];
#pragma unroll 16
    for (int k = 0; k < HID; k++) t = fmaf(zs[k], W1[k * HID + h], t);
    ts[h] = fmaxf(t, 0.f);
    __syncthreads();
    float o = b2[h];
#pragma unroll 16
    for (int k = 0; k < HID; k++) o = fmaf(ts[k], W2[k * HID + h], o);
    d_hB[n * HID + h] = fmaxf(o, 0.f);
}

// =====================================================================
// Launch 5: layer-2 MLP + g = h@M + write operand planes
//   H: exact 2-way fp16 split;  G: single fp16 (error absorbed, see analysis)
// =====================================================================
__global__ void mlp2_kernel(const float* __restrict__ W1, const float* __restrict__ b1,
                            const float* __restrict__ W2, const float* __restrict__ b2,
                            const float* __restrict__ M) {
    int n = blockIdx.x, h = threadIdx.x;
    __shared__ float zs[HID], ts[HID];
    zs[h] = d_hB[n * HID + h] + d_agg[n * HID + h];
    __syncthreads();
    float t = b1[h];
#pragma unroll 16
    for (int k = 0; k < HID; k++) t = fmaf(zs[k], W1[k * HID + h], t);
    ts[h] = fmaxf(t, 0.f);
    __syncthreads();
    float o = b2[h];
#pragma unroll 16
    for (int k = 0; k < HID; k++) o = fmaf(ts[k], W2[k * HID + h], o);
    __syncthreads();
    zs[h] = o;
    __syncthreads();
    float g = 0.f;
#pragma unroll 16
    for (int k = 0; k < HID; k++) g = fmaf(zs[k], M[k * HID + h], g);
    size_t off = (size_t)n * HID + h;
    __half h0 = __float2half(o);
    d_Hs[off] = h0;
    d_Hs[off + (size_t)NPAD * HID] = __float2half(o - __half2float(h0));
    d_Gs[off] = __float2half(g);
}

// =====================================================================
// Launch 6: E = exp(G@H^T - m_blk) via mma.sync fp16 2-term + partials
// CTA: 128x128 tile, 8 warps (2m x 4n), each warp 64x32
// =====================================================================
__global__ void __launch_bounds__(256) gemm_kernel() {
    extern __shared__ char smem[];
    uint32_t sbase = smem_u32(smem);
    int tid = threadIdx.x;
    int wid = tid >> 5, lane = tid & 31;
    int i0 = blockIdx.y * 128, j0 = blockIdx.x * 128;

    // load 3 tiles (A0 = G, B0/B1 = H splits), insert 16B/row pad
    {
        const uint4* gs = (const uint4*)d_Gs;
        const uint4* hs = (const uint4*)d_Hs;
        for (int t = tid; t < 3072; t += 256) {
            int s = t >> 10, o = t & 1023;
            int row = o >> 3, q = o & 7;
            uint4 v = (s == 0) ? gs[(size_t)(i0 + row) * 8 + q]
                               : hs[(size_t)(s - 1) * NPAD * 8 + (size_t)(j0 + row) * 8 + q];
            *(uint4*)(smem + s * SPLIT_TILE + row * ROWB + q * 16) = v;
        }
    }
    __syncthreads();

    int wm = wid >> 2, wn = wid & 3;
    float acc[4][4][4];
#pragma unroll
    for (int a = 0; a < 4; a++)
#pragma unroll
        for (int b = 0; b < 4; b++)
#pragma unroll
            for (int c = 0; c < 4; c++) acc[a][b][c] = 0.f;

    // A addressing: lanes 0-15 -> m rows, lanes 16-31 -> +16B k offset
    uint32_t lrow = (lane & 15), lcol = (lane >> 4) * 16;
    // B addressing (non-trans): 4 tiles = (n-octet, k-octet)
    int bg = lane >> 3, br = lane & 7;
    int b_noff = (bg >> 1) * 8 + br;
    int b_koff = (bg & 1) * 16;

    uint32_t abase = sbase + (wm * 64 + lrow) * ROWB + lcol;
    uint32_t bbase = sbase + SPLIT_TILE + (wn * 32 + b_noff) * ROWB + b_koff;

#pragma unroll
    for (int ks = 0; ks < 4; ks++) {
        uint32_t a[4][4];
#pragma unroll
        for (int mi = 0; mi < 4; mi++) ldsm4(a[mi], abase + mi * 16 * ROWB + ks * 32);
#pragma unroll
        for (int p = 0; p < 2; p++) {
            uint32_t bfr[2][4];
#pragma unroll
            for (int bi = 0; bi < 2; bi++)
                ldsm4(bfr[bi], bbase + p * SPLIT_TILE + bi * 16 * ROWB + ks * 32);
#pragma unroll
            for (int mi = 0; mi < 4; mi++)
#pragma unroll
                for (int ni = 0; ni < 4; ni++) {
                    int bi = ni >> 1, h = ni & 1;
                    mma16816(acc[mi][ni], a[mi], bfr[bi][h * 2], bfr[bi][h * 2 + 1]);
                }
        }
    }

    // epilogue: per (row, 32-col warp block): m, sum(exp), store fp16 exp values
    int q = lane >> 2, t2 = (lane & 3) * 2;
    bool edge_j = (blockIdx.x == NB - 1);
    size_t pidx_base = (size_t)(blockIdx.x * 4 + wn) * NPAD + i0;

#pragma unroll
    for (int mi = 0; mi < 4; mi++) {
#pragma unroll
        for (int half = 0; half < 2; half++) {
            int rl = wm * 64 + mi * 16 + q + half * 8;
            int gr = i0 + rl;
            float m = NEG, ssum = 0.f;
#pragma unroll
            for (int ni = 0; ni < 4; ni++) {
                int cg = j0 + wn * 32 + ni * 8 + t2;
                if (!edge_j || (cg < N_NODES))
                    m = fmaxf(m, fmaxf(acc[mi][ni][half * 2], acc[mi][ni][half * 2 + 1]));
            }
#pragma unroll
            for (int off = 1; off < 4; off <<= 1)
                m = fmaxf(m, __shfl_xor_sync(0xffffffffu, m, off));
            if (m > NEG) {
#pragma unroll
                for (int ni = 0; ni < 4; ni++) {
                    int cg = j0 + wn * 32 + ni * 8 + t2;
                    if (!edge_j || (cg < N_NODES)) {
                        float e0 = __expf(acc[mi][ni][half * 2] - m);
                        float e1 = __expf(acc[mi][ni][half * 2 + 1] - m);
                        ssum += e0 + e1;
                        if (gr < N_NODES)
                            *(__half2*)(d_E + (size_t)gr * N_NODES + cg) =
                                __floats2half2_rn(e0, e1);
                    }
                }
            }
#pragma unroll
            for (int off = 1; off < 4; off <<= 1)
                ssum += __shfl_xor_sync(0xffffffffu, ssum, off);
            if ((lane & 3) == 0) {
                d_pm[pidx_base + rl] = m;
                d_ps[pidx_base + rl] = ssum;
            }
        }
    }
}

// =====================================================================
// Launch 7: combine 316 col-block partials per row -> factors f = exp(m_blk-m)*inv
// =====================================================================
__global__ void combine_kernel() {
    int r = blockIdx.x * 256 + threadIdx.x;
    if (r >= N_NODES) return;
    float m = NEG;
    for (int t = 0; t < NCT; t++)
        m = fmaxf(m, d_pm[(size_t)t * NPAD + r]);
    float s = 0.f;
    for (int t = 0; t < NCT; t++)
        s += d_ps[(size_t)t * NPAD + r] * __expf(d_pm[(size_t)t * NPAD + r] - m);
    float inv = 1.f / s;
    for (int t = 0; t < NCT; t++)
        d_pf[(size_t)t * NPAD + r] = __expf(d_pm[(size_t)t * NPAD + r] - m) * inv;
}

// =====================================================================
// Launch 8: out[i][j] = E[i][j] * f[j>>5][i]
// =====================================================================
__global__ void finalize_kernel(float* __restrict__ out) {
    int i  = blockIdx.y;
    int j8 = (blockIdx.x * 256 + threadIdx.x) * 8;
    if (j8 >= N_NODES) return;
    float f = d_pf[(size_t)(j8 >> 5) * NPAD + i];
    uint4 e8 = *(const uint4*)(d_E + (size_t)i * N_NODES + j8);
    __half2 h0 = *(__half2*)&e8.x, h1 = *(__half2*)&e8.y;
    __half2 h2 = *(__half2*)&e8.z, h3 = *(__half2*)&e8.w;
    float2 f0 = __half22float2(h0), f1 = __half22float2(h1);
    float2 f2 = __half22float2(h2), f3 = __half22float2(h3);
    float* dst = out + (size_t)i * N_NODES + j8;
    *(float4*)dst       = make_float4(f0.x * f, f0.y * f, f1.x * f, f1.y * f);
    *(float4*)(dst + 4) = make_float4(f2.x * f, f2.y * f, f3.x * f, f3.y * f);
}

extern "C" void kernel_launch(void* const* d_in, const int* in_sizes, int n_in,
                              void* d_out, int out_size) {
    const float*    x     = (const float*)d_in[0];
    const float*    eattr = (const float*)d_in[1];
    const unsigned* eidx  = (const unsigned*)d_in[2];
    const float*    Win   = (const float*)d_in[3];
    const float*    bin   = (const float*)d_in[4];
    const float*    We    = (const float*)d_in[5];
    const float*    be    = (const float*)d_in[6];
    const float*    W1    = (const float*)d_in[7];
    const float*    b1    = (const float*)d_in[8];
    const float*    W2    = (const float*)d_in[9];
    const float*    b2    = (const float*)d_in[10];
    const float*    M     = (const float*)d_in[11];
    float*          out   = (float*)d_out;

    const int GEMM_SMEM = 3 * SPLIT_TILE;           // 55296
    cudaFuncSetAttribute(gemm_kernel, cudaFuncAttributeMaxDynamicSharedMemorySize, GEMM_SMEM);

    prep_kernel<<<6253, 256>>>(eidx, x, Win, bin);                     // #1
    edge_kernel<<<N_EDGES * 16 / 256, 256>>>(eattr, We, be, 0);        // #2
    mlp1_kernel<<<N_NODES, HID>>>(W1, b1, W2, b2);                     // #3
    edge_kernel<<<N_EDGES * 16 / 256, 256>>>(eattr, We, be, 1);        // #4
    mlp2_kernel<<<N_NODES, HID>>>(W1, b1, W2, b2, M);                  // #5
    dim3 ggrid(NB, NB);
    gemm_kernel<<<ggrid, 256, GEMM_SMEM>>>();                          // #6
    combine_kernel<<<(N_NODES + 255) / 256, 256>>>();                  // #7
    dim3 fgrid(5, N_NODES);                                            // 1250 threads/row over 8 cols
    finalize_kernel<<<fgrid, 256>>>(out);                              // #8
}

// round 8
// speedup vs baseline: 1.5134x; 1.0873x over previous
#include <cuda_runtime.h>
#include <cuda_fp16.h>
#include <cstdint>

#define N_NODES 10000
#define N_EDGES 320000
#define HID 64
#define NB 79
#define NPAD (NB * 128)          // 10112
#define NEG -3.0e38f
#define SPLIT_TILE 18432         // 128 rows * 144B padded row in smem
#define ROWB 144                 // smem row stride bytes (64 fp16 + 16 pad)
#define NCT (NB * 4)             // 316 col-blocks of 32

// ---------------- static device scratch ----------------
__device__ int   d_src[N_EDGES];
__device__ int   d_dst[N_EDGES];
__device__ float d_hA[N_NODES * HID];
__device__ float d_hB[N_NODES * HID];
__device__ float d_agg[N_NODES * HID];
// operands: G single fp16 plane; H 2-way fp16 split
__device__ __half d_Gs[NPAD * HID];
__device__ __half d_Hs[2 * NPAD * HID];
// per (32-col-block, row) softmax partials + factors
__device__ float d_pm[(size_t)NCT * NPAD];
__device__ float d_ps[(size_t)NCT * NPAD];
__device__ float d_pf[(size_t)NCT * NPAD];
__device__ __half d_E[(size_t)N_NODES * N_NODES];  // 200 MB exp scratch

// ---------------- helpers ----------------
__device__ __forceinline__ uint32_t smem_u32(const void* p) {
    uint32_t a;
    asm("{ .reg .u64 t; cvta.to.shared.u64 t, %1; cvt.u32.u64 %0, t; }" : "=r"(a) : "l"(p));
    return a;
}
__device__ __forceinline__ void ldsm4(uint32_t* r, uint32_t a) {
    asm volatile("ldmatrix.sync.aligned.m8n8.x4.shared.b16 {%0,%1,%2,%3}, [%4];"
                 : "=r"(r[0]), "=r"(r[1]), "=r"(r[2]), "=r"(r[3]) : "r"(a));
}
__device__ __forceinline__ void mma16816(float* c, const uint32_t* a, uint32_t b0, uint32_t b1) {
    asm volatile("mma.sync.aligned.m16n8k16.row.col.f32.f16.f16.f32 "
                 "{%0,%1,%2,%3},{%4,%5,%6,%7},{%8,%9},{%0,%1,%2,%3};"
                 : "+f"(c[0]), "+f"(c[1]), "+f"(c[2]), "+f"(c[3])
                 : "r"(a[0]), "r"(a[1]), "r"(a[2]), "r"(a[3]), "r"(b0), "r"(b1));
}
__device__ __forceinline__ void stg_cs32(void* p, uint32_t v) {
    asm volatile("st.global.cs.b32 [%0], %1;" :: "l"(p), "r"(v) : "memory");
}

// =====================================================================
// Launch 1: prep = edge convert (+width detect) | zero agg | node embed | zero split tails
// =====================================================================
__global__ void prep_kernel(const unsigned* __restrict__ raw,
                            const float* __restrict__ x,
                            const float* __restrict__ Win,
                            const float* __restrict__ bin) {
    int b = blockIdx.x, tid = threadIdx.x;
    if (b < 1250) {
        __shared__ unsigned s_is64;
        if (tid < 32) {
            unsigned acc = 0;
            for (int i = tid; i < 2048; i += 32) acc |= raw[2 * i + 1];
#pragma unroll
            for (int o = 16; o; o >>= 1) acc |= __shfl_xor_sync(0xffffffffu, acc, o);
            if (tid == 0) s_is64 = (acc == 0) ? 1u : 0u;
        }
        __syncthreads();
        int e = b * 256 + tid;
        if (s_is64) {
            d_src[e] = (int)raw[2 * e];
            d_dst[e] = (int)raw[2 * (N_EDGES + e)];
        } else {
            d_src[e] = (int)raw[e];
            d_dst[e] = (int)raw[N_EDGES + e];
        }
    } else if (b < 3750) {
        int i = (b - 1250) * 256 + tid;
        d_agg[i] = 0.f;
    } else if (b < 6250) {
        int local = b - 3750;
        int sub = tid >> 6, h = tid & 63;
        int n = local * 4 + sub;
        __shared__ float xs[4][24];
        if (h < 24) xs[sub][h] = x[n * 24 + h];
        __syncthreads();
        float a = bin[h];
#pragma unroll
        for (int k = 0; k < 24; k++) a = fmaf(xs[sub][k], Win[k * HID + h], a);
        d_hA[n * HID + h] = a;
    } else {
        int s = b - 6250;                            // 0..2: zero rows [N_NODES, NPAD)
        __half* zb = (s == 0) ? d_Gs : (d_Hs + (size_t)(s - 1) * NPAD * HID);
        uint4* p = (uint4*)(zb + (size_t)N_NODES * HID);
        for (int i = tid; i < (NPAD - N_NODES) * HID / 8; i += 256)
            p[i] = make_uint4(0, 0, 0, 0);
    }
}

// =====================================================================
// Launch 2/4: agg[dst] += relu(h[src] + edge_attr@We + be)
// =====================================================================
__global__ void edge_kernel(const float* __restrict__ eattr,
                            const float* __restrict__ We,
                            const float* __restrict__ be, int sel) {
    int idx = blockIdx.x * 256 + threadIdx.x;
    int e = idx >> 4;
    int c = (idx & 15) * 4;
    const float* hin = sel ? d_hB : d_hA;
    int s = d_src[e], d = d_dst[e];
    float2 a  = *(const float2*)(eattr + 2 * e);
    float4 h4 = *(const float4*)(hin + s * HID + c);
    float4 w0 = *(const float4*)(We + c);
    float4 w1 = *(const float4*)(We + HID + c);
    float4 b4 = *(const float4*)(be + c);
    float v0 = fmaxf(h4.x + fmaf(a.x, w0.x, fmaf(a.y, w1.x, b4.x)), 0.f);
    float v1 = fmaxf(h4.y + fmaf(a.x, w0.y, fmaf(a.y, w1.y, b4.y)), 0.f);
    float v2 = fmaxf(h4.z + fmaf(a.x, w0.z, fmaf(a.y, w1.z, b4.z)), 0.f);
    float v3 = fmaxf(h4.w + fmaf(a.x, w0.w, fmaf(a.y, w1.w, b4.w)), 0.f);
    asm volatile("red.global.add.v4.f32 [%0], {%1,%2,%3,%4};"
                 :: "l"(d_agg + d * HID + c), "f"(v0), "f"(v1), "f"(v2), "f"(v3) : "memory");
}

// =====================================================================
// Launch 3: layer-1 MLP (relu out) + re-zero agg
// =====================================================================
__global__ void mlp1_kernel(const float* __restrict__ W1, const float* __restrict__ b1,
                            const float* __restrict__ W2, const float* __restrict__ b2) {
    int n = blockIdx.x, h = threadIdx.x;
    __shared__ float zs[HID], ts[HID];
    zs[h] = d_hA[n * HID + h] + d_agg[n * HID + h];
    d_agg[n * HID + h] = 0.f;
    __syncthreads();
    float t = b1[h];
#pragma unroll 16
    for (int k = 0; k < HID; k++) t = fmaf(zs[k], W1[k * HID + h], t);
    ts[h] = fmaxf(t, 0.f);
    __syncthreads();
    float o = b2[h];
#pragma unroll 16
    for (int k = 0; k < HID; k++) o = fmaf(ts[k], W2[k * HID + h], o);
    d_hB[n * HID + h] = fmaxf(o, 0.f);
}

// =====================================================================
// Launch 5: layer-2 MLP + g = h@M + write operand planes
// =====================================================================
__global__ void mlp2_kernel(const float* __restrict__ W1, const float* __restrict__ b1,
                            const float* __restrict__ W2, const float* __restrict__ b2,
                            const float* __restrict__ M) {
    int n = blockIdx.x, h = threadIdx.x;
    __shared__ float zs[HID], ts[HID];
    zs[h] = d_hB[n * HID + h] + d_agg[n * HID + h];
    __syncthreads();
    float t = b1[h];
#pragma unroll 16
    for (int k = 0; k < HID; k++) t = fmaf(zs[k], W1[k * HID + h], t);
    ts[h] = fmaxf(t, 0.f);
    __syncthreads();
    float o = b2[h];
#pragma unroll 16
    for (int k = 0; k < HID; k++) o = fmaf(ts[k], W2[k * HID + h], o);
    __syncthreads();
    zs[h] = o;
    __syncthreads();
    float g = 0.f;
#pragma unroll 16
    for (int k = 0; k < HID; k++) g = fmaf(zs[k], M[k * HID + h], g);
    size_t off = (size_t)n * HID + h;
    __half h0 = __float2half(o);
    d_Hs[off] = h0;
    d_Hs[off + (size_t)NPAD * HID] = __float2half(o - __half2float(h0));
    d_Gs[off] = __float2half(g);
}

// =====================================================================
// Launch 6: E = exp(G@H^T - m_blk) via mma.sync fp16 2-term + partials
// CTA: 128x128 tile, 8 warps (2m x 4n), each warp 64x32; 2 CTAs/SM
// =====================================================================
__global__ void __launch_bounds__(256, 2) gemm_kernel() {
    extern __shared__ char smem[];
    uint32_t sbase = smem_u32(smem);
    int tid = threadIdx.x;
    int wid = tid >> 5, lane = tid & 31;
    int i0 = blockIdx.y * 128, j0 = blockIdx.x * 128;

    // load 3 tiles (A0 = G, B0/B1 = H splits), insert 16B/row pad
    {
        const uint4* gs = (const uint4*)d_Gs;
        const uint4* hs = (const uint4*)d_Hs;
        for (int t = tid; t < 3072; t += 256) {
            int s = t >> 10, o = t & 1023;
            int row = o >> 3, q = o & 7;
            uint4 v = (s == 0) ? gs[(size_t)(i0 + row) * 8 + q]
                               : hs[(size_t)(s - 1) * NPAD * 8 + (size_t)(j0 + row) * 8 + q];
            *(uint4*)(smem + s * SPLIT_TILE + row * ROWB + q * 16) = v;
        }
    }
    __syncthreads();

    int wm = wid >> 2, wn = wid & 3;
    float acc[4][4][4];
#pragma unroll
    for (int a = 0; a < 4; a++)
#pragma unroll
        for (int b = 0; b < 4; b++)
#pragma unroll
            for (int c = 0; c < 4; c++) acc[a][b][c] = 0.f;

    // A addressing: lanes 0-15 -> m rows, lanes 16-31 -> +16B k offset
    uint32_t lrow = (lane & 15), lcol = (lane >> 4) * 16;
    // B addressing (non-trans): 4 tiles = (n-octet, k-octet)
    int bg = lane >> 3, br = lane & 7;
    int b_noff = (bg >> 1) * 8 + br;
    int b_koff = (bg & 1) * 16;

    uint32_t abase = sbase + (wm * 64 + lrow) * ROWB + lcol;
    uint32_t bbase = sbase + SPLIT_TILE + (wn * 32 + b_noff) * ROWB + b_koff;

#pragma unroll
    for (int ks = 0; ks < 4; ks++) {
        uint32_t a[4][4];
#pragma unroll
        for (int mi = 0; mi < 4; mi++) ldsm4(a[mi], abase + mi * 16 * ROWB + ks * 32);
#pragma unroll
        for (int p = 0; p < 2; p++) {
            uint32_t bfr[2][4];
#pragma unroll
            for (int bi = 0; bi < 2; bi++)
                ldsm4(bfr[bi], bbase + p * SPLIT_TILE + bi * 16 * ROWB + ks * 32);
#pragma unroll
            for (int mi = 0; mi < 4; mi++)
#pragma unroll
                for (int ni = 0; ni < 4; ni++) {
                    int bi = ni >> 1, h = ni & 1;
                    mma16816(acc[mi][ni], a[mi], bfr[bi][h * 2], bfr[bi][h * 2 + 1]);
                }
        }
    }

    // epilogue: per (row, 32-col warp block): m, sum(exp), store fp16 exp values
    int q = lane >> 2, t2 = (lane & 3) * 2;
    bool edge_j = (blockIdx.x == NB - 1);
    size_t pidx_base = (size_t)(blockIdx.x * 4 + wn) * NPAD + i0;

#pragma unroll
    for (int mi = 0; mi < 4; mi++) {
#pragma unroll
        for (int half = 0; half < 2; half++) {
            int rl = wm * 64 + mi * 16 + q + half * 8;
            int gr = i0 + rl;
            float m = NEG, ssum = 0.f;
#pragma unroll
            for (int ni = 0; ni < 4; ni++) {
                int cg = j0 + wn * 32 + ni * 8 + t2;
                if (!edge_j || (cg < N_NODES))
                    m = fmaxf(m, fmaxf(acc[mi][ni][half * 2], acc[mi][ni][half * 2 + 1]));
            }
#pragma unroll
            for (int off = 1; off < 4; off <<= 1)
                m = fmaxf(m, __shfl_xor_sync(0xffffffffu, m, off));
            if (m > NEG) {
#pragma unroll
                for (int ni = 0; ni < 4; ni++) {
                    int cg = j0 + wn * 32 + ni * 8 + t2;
                    if (!edge_j || (cg < N_NODES)) {
                        float e0 = __expf(acc[mi][ni][half * 2] - m);
                        float e1 = __expf(acc[mi][ni][half * 2 + 1] - m);
                        ssum += e0 + e1;
                        if (gr < N_NODES) {
                            __half2 hv = __floats2half2_rn(e0, e1);
                            stg_cs32(d_E + (size_t)gr * N_NODES + cg,
                                     *(uint32_t*)&hv);
                        }
                    }
                }
            }
#pragma unroll
            for (int off = 1; off < 4; off <<= 1)
                ssum += __shfl_xor_sync(0xffffffffu, ssum, off);
            if ((lane & 3) == 0) {
                d_pm[pidx_base + rl] = m;
                d_ps[pidx_base + rl] = ssum;
            }
        }
    }
}

// =====================================================================
// Launch 7: combine 316 col-block partials per row -> factors f = exp(m_blk-m)*inv
// =====================================================================
__global__ void combine_kernel() {
    int r = blockIdx.x * 256 + threadIdx.x;
    if (r >= N_NODES) return;
    float m = NEG;
    for (int t = 0; t < NCT; t++)
        m = fmaxf(m, d_pm[(size_t)t * NPAD + r]);
    float s = 0.f;
    for (int t = 0; t < NCT; t++)
        s += d_ps[(size_t)t * NPAD + r] * __expf(d_pm[(size_t)t * NPAD + r] - m);
    float inv = 1.f / s;
    for (int t = 0; t < NCT; t++)
        d_pf[(size_t)t * NPAD + r] = __expf(d_pm[(size_t)t * NPAD + r] - m) * inv;
}

// =====================================================================
// Launch 8: out[i][j] = E[i][j] * f[j>>5][i]   (streaming loads/stores)
// =====================================================================
__global__ void finalize_kernel(float* __restrict__ out) {
    int i  = blockIdx.y;
    int j8 = (blockIdx.x * 256 + threadIdx.x) * 8;
    if (j8 >= N_NODES) return;
    float f = d_pf[(size_t)(j8 >> 5) * NPAD + i];
    uint4 e8 = __ldcs((const uint4*)(d_E + (size_t)i * N_NODES + j8));
    __half2 h0 = *(__half2*)&e8.x, h1 = *(__half2*)&e8.y;
    __half2 h2 = *(__half2*)&e8.z, h3 = *(__half2*)&e8.w;
    float2 f0 = __half22float2(h0), f1 = __half22float2(h1);
    float2 f2 = __half22float2(h2), f3 = __half22float2(h3);
    float* dst = out + (size_t)i * N_NODES + j8;
    __stcs((float4*)dst,       make_float4(f0.x * f, f0.y * f, f1.x * f, f1.y * f));
    __stcs((float4*)(dst + 4), make_float4(f2.x * f, f2.y * f, f3.x * f, f3.y * f));
}

extern "C" void kernel_launch(void* const* d_in, const int* in_sizes, int n_in,
                              void* d_out, int out_size) {
    const float*    x     = (const float*)d_in[0];
    const float*    eattr = (const float*)d_in[1];
    const unsigned* eidx  = (const unsigned*)d_in[2];
    const float*    Win   = (const float*)d_in[3];
    const float*    bin   = (const float*)d_in[4];
    const float*    We    = (const float*)d_in[5];
    const float*    be    = (const float*)d_in[6];
    const float*    W1    = (const float*)d_in[7];
    const float*    b1    = (const float*)d_in[8];
    const float*    W2    = (const float*)d_in[9];
    const float*    b2    = (const float*)d_in[10];
    const float*    M     = (const float*)d_in[11];
    float*          out   = (float*)d_out;

    const int GEMM_SMEM = 3 * SPLIT_TILE;           // 55296
    cudaFuncSetAttribute(gemm_kernel, cudaFuncAttributeMaxDynamicSharedMemorySize, GEMM_SMEM);

    prep_kernel<<<6253, 256>>>(eidx, x, Win, bin);                     // #1
    edge_kernel<<<N_EDGES * 16 / 256, 256>>>(eattr, We, be, 0);        // #2
    mlp1_kernel<<<N_NODES, HID>>>(W1, b1, W2, b2);                     // #3
    edge_kernel<<<N_EDGES * 16 / 256, 256>>>(eattr, We, be, 1);        // #4
    mlp2_kernel<<<N_NODES, HID>>>(W1, b1, W2, b2, M);                  // #5
    dim3 ggrid(NB, NB);
    gemm_kernel<<<ggrid, 256, GEMM_SMEM>>>();                          // #6
    combine_kernel<<<(N_NODES + 255) / 256, 256>>>();                  // #7
    dim3 fgrid(5, N_NODES);
    finalize_kernel<<<fgrid, 256>>>(out);                              // #8
}

// round 9
// speedup vs baseline: 1.6446x; 1.0867x over previous
#include <cuda_runtime.h>
#include <cuda_fp16.h>
#include <cstdint>

#define N_NODES 10000
#define N_EDGES 320000
#define HID 64
#define NB 79
#define NPAD (NB * 128)          // 10112
#define NEG -3.0e38f
#define SPLIT_TILE 18432         // 128 rows * 144B padded row in smem
#define ROWB 144                 // smem row stride bytes (64 fp16 + 16 pad)
#define NCT (NB * 4)             // 316 col-blocks of 32

// ---------------- static device scratch ----------------
__device__ int   d_src[N_EDGES];
__device__ int   d_dst[N_EDGES];
__device__ float d_hA[N_NODES * HID];
__device__ float d_hB[N_NODES * HID];
__device__ float d_agg[N_NODES * HID];
// fp16 operand planes (single-term)
__device__ __half d_Gs[NPAD * HID];
__device__ __half d_Hs[NPAD * HID];
// per (32-col-block, row) softmax partials + factors
__device__ float d_pm[(size_t)NCT * NPAD];
__device__ float d_ps[(size_t)NCT * NPAD];
__device__ float d_pf[(size_t)NCT * NPAD];
__device__ __half d_E[(size_t)N_NODES * N_NODES];  // 200 MB exp scratch

// ---------------- helpers ----------------
__device__ __forceinline__ uint32_t smem_u32(const void* p) {
    uint32_t a;
    asm("{ .reg .u64 t; cvta.to.shared.u64 t, %1; cvt.u32.u64 %0, t; }" : "=r"(a) : "l"(p));
    return a;
}
__device__ __forceinline__ void ldsm4(uint32_t* r, uint32_t a) {
    asm volatile("ldmatrix.sync.aligned.m8n8.x4.shared.b16 {%0,%1,%2,%3}, [%4];"
                 : "=r"(r[0]), "=r"(r[1]), "=r"(r[2]), "=r"(r[3]) : "r"(a));
}
__device__ __forceinline__ void mma16816(float* c, const uint32_t* a, uint32_t b0, uint32_t b1) {
    asm volatile("mma.sync.aligned.m16n8k16.row.col.f32.f16.f16.f32 "
                 "{%0,%1,%2,%3},{%4,%5,%6,%7},{%8,%9},{%0,%1,%2,%3};"
                 : "+f"(c[0]), "+f"(c[1]), "+f"(c[2]), "+f"(c[3])
                 : "r"(a[0]), "r"(a[1]), "r"(a[2]), "r"(a[3]), "r"(b0), "r"(b1));
}
__device__ __forceinline__ void stg_cs32(void* p, uint32_t v) {
    asm volatile("st.global.cs.b32 [%0], %1;" :: "l"(p), "r"(v) : "memory");
}

// =====================================================================
// Launch 1: prep = edge convert (+width detect) | zero agg | node embed | zero plane tails
// =====================================================================
__global__ void prep_kernel(const unsigned* __restrict__ raw,
                            const float* __restrict__ x,
                            const float* __restrict__ Win,
                            const float* __restrict__ bin) {
    int b = blockIdx.x, tid = threadIdx.x;
    if (b < 1250) {
        __shared__ unsigned s_is64;
        if (tid < 32) {
            unsigned acc = 0;
            for (int i = tid; i < 2048; i += 32) acc |= raw[2 * i + 1];
#pragma unroll
            for (int o = 16; o; o >>= 1) acc |= __shfl_xor_sync(0xffffffffu, acc, o);
            if (tid == 0) s_is64 = (acc == 0) ? 1u : 0u;
        }
        __syncthreads();
        int e = b * 256 + tid;
        if (s_is64) {
            d_src[e] = (int)raw[2 * e];
            d_dst[e] = (int)raw[2 * (N_EDGES + e)];
        } else {
            d_src[e] = (int)raw[e];
            d_dst[e] = (int)raw[N_EDGES + e];
        }
    } else if (b < 3750) {
        int i = (b - 1250) * 256 + tid;
        d_agg[i] = 0.f;
    } else if (b < 6250) {
        int local = b - 3750;
        int sub = tid >> 6, h = tid & 63;
        int n = local * 4 + sub;
        __shared__ float xs[4][24];
        if (h < 24) xs[sub][h] = x[n * 24 + h];
        __syncthreads();
        float a = bin[h];
#pragma unroll
        for (int k = 0; k < 24; k++) a = fmaf(xs[sub][k], Win[k * HID + h], a);
        d_hA[n * HID + h] = a;
    } else {
        int s = b - 6250;                            // 0..1: zero rows [N_NODES, NPAD)
        __half* zb = (s == 0) ? d_Gs : d_Hs;
        uint4* p = (uint4*)(zb + (size_t)N_NODES * HID);
        for (int i = tid; i < (NPAD - N_NODES) * HID / 8; i += 256)
            p[i] = make_uint4(0, 0, 0, 0);
    }
}

// =====================================================================
// Launch 2/4: agg[dst] += relu(h[src] + edge_attr@We + be)
// =====================================================================
__global__ void edge_kernel(const float* __restrict__ eattr,
                            const float* __restrict__ We,
                            const float* __restrict__ be, int sel) {
    int idx = blockIdx.x * 256 + threadIdx.x;
    int e = idx >> 4;
    int c = (idx & 15) * 4;
    const float* hin = sel ? d_hB : d_hA;
    int s = d_src[e], d = d_dst[e];
    float2 a  = *(const float2*)(eattr + 2 * e);
    float4 h4 = *(const float4*)(hin + s * HID + c);
    float4 w0 = *(const float4*)(We + c);
    float4 w1 = *(const float4*)(We + HID + c);
    float4 b4 = *(const float4*)(be + c);
    float v0 = fmaxf(h4.x + fmaf(a.x, w0.x, fmaf(a.y, w1.x, b4.x)), 0.f);
    float v1 = fmaxf(h4.y + fmaf(a.x, w0.y, fmaf(a.y, w1.y, b4.y)), 0.f);
    float v2 = fmaxf(h4.z + fmaf(a.x, w0.z, fmaf(a.y, w1.z, b4.z)), 0.f);
    float v3 = fmaxf(h4.w + fmaf(a.x, w0.w, fmaf(a.y, w1.w, b4.w)), 0.f);
    asm volatile("red.global.add.v4.f32 [%0], {%1,%2,%3,%4};"
                 :: "l"(d_agg + d * HID + c), "f"(v0), "f"(v1), "f"(v2), "f"(v3) : "memory");
}

// =====================================================================
// Launch 3: layer-1 MLP (relu out) + re-zero agg
// =====================================================================
__global__ void mlp1_kernel(const float* __restrict__ W1, const float* __restrict__ b1,
                            const float* __restrict__ W2, const float* __restrict__ b2) {
    int n = blockIdx.x, h = threadIdx.x;
    __shared__ float zs[HID], ts[HID];
    zs[h] = d_hA[n * HID + h] + d_agg[n * HID + h];
    d_agg[n * HID + h] = 0.f;
    __syncthreads();
    float t = b1[h];
#pragma unroll 16
    for (int k = 0; k < HID; k++) t = fmaf(zs[k], W1[k * HID + h], t);
    ts[h] = fmaxf(t, 0.f);
    __syncthreads();
    float o = b2[h];
#pragma unroll 16
    for (int k = 0; k < HID; k++) o = fmaf(ts[k], W2[k * HID + h], o);
    d_hB[n * HID + h] = fmaxf(o, 0.f);
}

// =====================================================================
// Launch 5: layer-2 MLP + g = h@M + write fp16 operand planes
// =====================================================================
__global__ void mlp2_kernel(const float* __restrict__ W1, const float* __restrict__ b1,
                            const float* __restrict__ W2, const float* __restrict__ b2,
                            const float* __restrict__ M) {
    int n = blockIdx.x, h = threadIdx.x;
    __shared__ float zs[HID], ts[HID];
    zs[h] = d_hB[n * HID + h] + d_agg[n * HID + h];
    __syncthreads();
    float t = b1[h];
#pragma unroll 16
    for (int k = 0; k < HID; k++) t = fmaf(zs[k], W1[k * HID + h], t);
    ts[h] = fmaxf(t, 0.f);
    __syncthreads();
    float o = b2[h];
#pragma unroll 16
    for (int k = 0; k < HID; k++) o = fmaf(ts[k], W2[k * HID + h], o);
    __syncthreads();
    zs[h] = o;
    __syncthreads();
    float g = 0.f;
#pragma unroll 16
    for (int k = 0; k < HID; k++) g = fmaf(zs[k], M[k * HID + h], g);
    size_t off = (size_t)n * HID + h;
    d_Hs[off] = __float2half(o);
    d_Gs[off] = __float2half(g);
}

// =====================================================================
// Launch 6: E = exp(G@H^T - m_blk) via mma.sync fp16 single-term + partials
// CTA: 128x128 tile, 8 warps (2m x 4n), each warp 64x32; 2 CTAs/SM
// =====================================================================
__global__ void __launch_bounds__(256, 2) gemm_kernel() {
    extern __shared__ char smem[];
    uint32_t sbase = smem_u32(smem);
    int tid = threadIdx.x;
    int wid = tid >> 5, lane = tid & 31;
    int i0 = blockIdx.y * 128, j0 = blockIdx.x * 128;

    // load 2 tiles (A = G, B = H), insert 16B/row pad
    {
        const uint4* gs = (const uint4*)d_Gs;
        const uint4* hs = (const uint4*)d_Hs;
        for (int t = tid; t < 2048; t += 256) {
            int s = t >> 10, o = t & 1023;
            int row = o >> 3, q = o & 7;
            uint4 v = (s == 0) ? gs[(size_t)(i0 + row) * 8 + q]
                               : hs[(size_t)(j0 + row) * 8 + q];
            *(uint4*)(smem + s * SPLIT_TILE + row * ROWB + q * 16) = v;
        }
    }
    __syncthreads();

    int wm = wid >> 2, wn = wid & 3;
    float acc[4][4][4];
#pragma unroll
    for (int a = 0; a < 4; a++)
#pragma unroll
        for (int b = 0; b < 4; b++)
#pragma unroll
            for (int c = 0; c < 4; c++) acc[a][b][c] = 0.f;

    // A addressing: lanes 0-15 -> m rows, lanes 16-31 -> +16B k offset
    uint32_t lrow = (lane & 15), lcol = (lane >> 4) * 16;
    // B addressing (non-trans): 4 tiles = (n-octet, k-octet)
    int bg = lane >> 3, br = lane & 7;
    int b_noff = (bg >> 1) * 8 + br;
    int b_koff = (bg & 1) * 16;

    uint32_t abase = sbase + (wm * 64 + lrow) * ROWB + lcol;
    uint32_t bbase = sbase + SPLIT_TILE + (wn * 32 + b_noff) * ROWB + b_koff;

#pragma unroll
    for (int ks = 0; ks < 4; ks++) {
        uint32_t a[4][4];
#pragma unroll
        for (int mi = 0; mi < 4; mi++) ldsm4(a[mi], abase + mi * 16 * ROWB + ks * 32);
        uint32_t bfr[2][4];
#pragma unroll
        for (int bi = 0; bi < 2; bi++)
            ldsm4(bfr[bi], bbase + bi * 16 * ROWB + ks * 32);
#pragma unroll
        for (int mi = 0; mi < 4; mi++)
#pragma unroll
            for (int ni = 0; ni < 4; ni++) {
                int bi = ni >> 1, h = ni & 1;
                mma16816(acc[mi][ni], a[mi], bfr[bi][h * 2], bfr[bi][h * 2 + 1]);
            }
    }

    // epilogue: per (row, 32-col warp block): m, sum(exp), store fp16 exp values
    int q = lane >> 2, t2 = (lane & 3) * 2;
    bool edge_j = (blockIdx.x == NB - 1);
    size_t pidx_base = (size_t)(blockIdx.x * 4 + wn) * NPAD + i0;

#pragma unroll
    for (int mi = 0; mi < 4; mi++) {
#pragma unroll
        for (int half = 0; half < 2; half++) {
            int rl = wm * 64 + mi * 16 + q + half * 8;
            int gr = i0 + rl;
            float m = NEG, ssum = 0.f;
#pragma unroll
            for (int ni = 0; ni < 4; ni++) {
                int cg = j0 + wn * 32 + ni * 8 + t2;
                if (!edge_j || (cg < N_NODES))
                    m = fmaxf(m, fmaxf(acc[mi][ni][half * 2], acc[mi][ni][half * 2 + 1]));
            }
#pragma unroll
            for (int off = 1; off < 4; off <<= 1)
                m = fmaxf(m, __shfl_xor_sync(0xffffffffu, m, off));
            if (m > NEG) {
#pragma unroll
                for (int ni = 0; ni < 4; ni++) {
                    int cg = j0 + wn * 32 + ni * 8 + t2;
                    if (!edge_j || (cg < N_NODES)) {
                        float e0 = __expf(acc[mi][ni][half * 2] - m);
                        float e1 = __expf(acc[mi][ni][half * 2 + 1] - m);
                        ssum += e0 + e1;
                        if (gr < N_NODES) {
                            __half2 hv = __floats2half2_rn(e0, e1);
                            stg_cs32(d_E + (size_t)gr * N_NODES + cg,
                                     *(uint32_t*)&hv);
                        }
                    }
                }
            }
#pragma unroll
            for (int off = 1; off < 4; off <<= 1)
                ssum += __shfl_xor_sync(0xffffffffu, ssum, off);
            if ((lane & 3) == 0) {
                d_pm[pidx_base + rl] = m;
                d_ps[pidx_base + rl] = ssum;
            }
        }
    }
}

// =====================================================================
// Launch 7: combine 316 col-block partials per row -> factors f = exp(m_blk-m)*inv
// =====================================================================
__global__ void combine_kernel() {
    int r = blockIdx.x * 256 + threadIdx.x;
    if (r >= N_NODES) return;
    float m = NEG;
    for (int t = 0; t < NCT; t++)
        m = fmaxf(m, d_pm[(size_t)t * NPAD + r]);
    float s = 0.f;
    for (int t = 0; t < NCT; t++)
        s += d_ps[(size_t)t * NPAD + r] * __expf(d_pm[(size_t)t * NPAD + r] - m);
    float inv = 1.f / s;
    for (int t = 0; t < NCT; t++)
        d_pf[(size_t)t * NPAD + r] = __expf(d_pm[(size_t)t * NPAD + r] - m) * inv;
}

// =====================================================================
// Launch 8: out[i][j] = E[i][j] * f[j>>5][i]   (streaming loads/stores)
// =====================================================================
__global__ void finalize_kernel(float* __restrict__ out) {
    int i  = blockIdx.y;
    int j8 = (blockIdx.x * 256 + threadIdx.x) * 8;
    if (j8 >= N_NODES) return;
    float f = d_pf[(size_t)(j8 >> 5) * NPAD + i];
    uint4 e8 = __ldcs((const uint4*)(d_E + (size_t)i * N_NODES + j8));
    __half2 h0 = *(__half2*)&e8.x, h1 = *(__half2*)&e8.y;
    __half2 h2 = *(__half2*)&e8.z, h3 = *(__half2*)&e8.w;
    float2 f0 = __half22float2(h0), f1 = __half22float2(h1);
    float2 f2 = __half22float2(h2), f3 = __half22float2(h3);
    float* dst = out + (size_t)i * N_NODES + j8;
    __stcs((float4*)dst,       make_float4(f0.x * f, f0.y * f, f1.x * f, f1.y * f));
    __stcs((float4*)(dst + 4), make_float4(f2.x * f, f2.y * f, f3.x * f, f3.y * f));
}

extern "C" void kernel_launch(void* const* d_in, const int* in_sizes, int n_in,
                              void* d_out, int out_size) {
    const float*    x     = (const float*)d_in[0];
    const float*    eattr = (const float*)d_in[1];
    const unsigned* eidx  = (const unsigned*)d_in[2];
    const float*    Win   = (const float*)d_in[3];
    const float*    bin   = (const float*)d_in[4];
    const float*    We    = (const float*)d_in[5];
    const float*    be    = (const float*)d_in[6];
    const float*    W1    = (const float*)d_in[7];
    const float*    b1    = (const float*)d_in[8];
    const float*    W2    = (const float*)d_in[9];
    const float*    b2    = (const float*)d_in[10];
    const float*    M     = (const float*)d_in[11];
    float*          out   = (float*)d_out;

    const int GEMM_SMEM = 2 * SPLIT_TILE;           // 36864
    cudaFuncSetAttribute(gemm_kernel, cudaFuncAttributeMaxDynamicSharedMemorySize, GEMM_SMEM);

    prep_kernel<<<6252, 256>>>(eidx, x, Win, bin);                     // #1
    edge_kernel<<<N_EDGES * 16 / 256, 256>>>(eattr, We, be, 0);        // #2
    mlp1_kernel<<<N_NODES, HID>>>(W1, b1, W2, b2);                     // #3
    edge_kernel<<<N_EDGES * 16 / 256, 256>>>(eattr, We, be, 1);        // #4
    mlp2_kernel<<<N_NODES, HID>>>(W1, b1, W2, b2, M);                  // #5
    dim3 ggrid(NB, NB);
    gemm_kernel<<<ggrid, 256, GEMM_SMEM>>>();                          // #6
    combine_kernel<<<(N_NODES + 255) / 256, 256>>>();                  // #7
    dim3 fgrid(5, N_NODES);
    finalize_kernel<<<fgrid, 256>>>(out);                              // #8
}